// round 17
// baseline (speedup 1.0000x reference)
#include <cuda_runtime.h>
#include <math.h>

#define BB 8
#define GG 16
#define PP 64
#define IMH 640
#define IMW 640
#define SZ 32
#define NITEMS (BB*PP*3)
#define NPBLOCKS (148*4)

// Gaussian window weights for WIN=11, sigma=1.5 (exp(-d^2/4.5), normalized),
// accurate to ~1e-8 vs the float64 reference; constexpr -> FFMA immediates.
__device__ constexpr float GW[6] = {
    0.26601172f,   // |d|=0
    0.21300554f,   // |d|=1
    0.10936070f,   // |d|=2
    0.03600077f,   // |d|=3
    0.00759876f,   // |d|=4
    0.00102838f    // |d|=5
};

__device__ double d_total = 0.0;
__device__ double d_cnt   = 0.0;
__device__ unsigned int d_done = 0;
__device__ unsigned int d_work = 0;

// Per-axis bilinear sampling coords, same arithmetic order as reference
__device__ __forceinline__ void axis_coord(float origin, float len, int maxdim, int i,
                                           int& lo, int& hi, float& wq) {
    float lm = fmaxf(len - 1.0f, 0.0f);
    float s  = fminf(fmaxf(((float)i + 0.5f) * (len / (float)SZ) - 0.5f, 0.0f), lm);
    float sf = floorf(s);
    wq = s - sf;
    float vlo = sf + origin;
    float vhi = fminf(sf + 1.0f, lm) + origin;
    lo = (int)fminf(fmaxf(vlo, 0.0f), (float)(maxdim - 1));
    hi = (int)fminf(fmaxf(vhi, 0.0f), (float)(maxdim - 1));
}

__device__ __forceinline__ float lerpf(float a, float b, float w) {
    return fmaf(w, b - a, a);
}

// Crop the two pixels (row, c0) and (row, c0+1) of one box. Self-contained so
// its temporaries die before the barrier (keeps hot-loop regs low).
__device__ __forceinline__ void crop_pair(const float* __restrict__ imc,
                                          const float* __restrict__ box,
                                          int row, int c0,
                                          float& vA, float& vB) {
    float bx = box[0], by = box[1], bw = box[2], bh = box[3];
    float x0 = floorf(bx), y0 = floorf(by);
    float w  = floorf(bx + bw) - x0;
    float h  = floorf(by + bh) - y0;
    int xlo0, xhi0, xlo1, xhi1, ylo, yhi;
    float wx0, wx1, wy;
    axis_coord(x0, w, IMW, c0,     xlo0, xhi0, wx0);
    axis_coord(x0, w, IMW, c0 + 1, xlo1, xhi1, wx1);
    axis_coord(y0, h, IMH, row,    ylo,  yhi,  wy);
    int blo = ylo*IMW, bhi = yhi*IMW;
    {
        float tl = __ldg(imc + blo + xlo0);
        float tr = __ldg(imc + blo + xhi0);
        float bl = __ldg(imc + bhi + xlo0);
        float br = __ldg(imc + bhi + xhi0);
        vA = lerpf(lerpf(tl, tr, wx0), lerpf(bl, br, wx0), wy);
    }
    {
        float tl = __ldg(imc + blo + xlo1);
        float tr = __ldg(imc + blo + xhi1);
        float bl = __ldg(imc + bhi + xlo1);
        float br = __ldg(imc + bhi + xhi1);
        vB = lerpf(lerpf(tl, tr, wx1), lerpf(bl, br, wx1), wy);
    }
}

// Padded H-field buffer: rows -5..36 (42 rows), index = (realrow+5)*32+lane.
// Pad rows are zero and never rewritten -> V-pass needs no row guards.
#define HROWS 42

__global__ void __launch_bounds__(512, 4)
fused_kernel(const float* __restrict__ gt,
             const float* __restrict__ pr,
             const float* __restrict__ imgs,
             float* __restrict__ out) {
    const unsigned FULL = 0xffffffffu;
    int t = threadIdx.x;
    int lane = t & 31;
    int warp = t >> 5;          // 0..15
    int r0 = warp * 2;          // warp owns rows r0, r0+1
    // H/crop mapping: half-warp hw covers row r0+hw; thread owns cols 2cp,2cp+1
    int hw = lane >> 4;
    int cp = lane & 15;
    int hrow = r0 + hw;
    int c0 = cp * 2;

    __shared__ int      s_item[2];         // parity-indexed publication slots
    __shared__ unsigned s_mask[2];
    __shared__ float4   Hb[2][HROWS*SZ];   // 4 fields packed, double-buffered, 43 KB
    __shared__ float    sred[16];
    __shared__ bool     s_last;

    // zero the pad rows (rows -5..-1 and 32..36) of both buffers, once per block
    if (t < 320) {
        int prow = t >> 5;                       // 0..9
        int row  = (prow < 5) ? prow : prow + 32;
        int k = row * SZ + (t & 31);
        float4 z = make_float4(0.0f, 0.0f, 0.0f, 0.0f);
        Hb[0][k] = z; Hb[1][k] = z;
    }

    const float C1 = 6.5025f;     // (0.01*255)^2
    const float C2x2 = 117.045f;  // 2*(0.03*255)^2
    float accf   = 0.0f;   // per-thread loss accumulator, carried across items
    int   cntloc = 0;      // masked-pair count (t==0 meaningful), c==0 items only
    int   it     = 0;      // publication-slot parity

    // ---- persistent work loop: items are (pred, channel) ----
    while (true) {
        // warp 0: pop next item and compute the 16-gt IoU mask via ballot.
        // Parity slots: this write targets the slot last read two iterations
        // ago; the intervening barrier orders it, so ONE barrier per item.
        if (warp == 0) {
            int item;
            if (lane == 0) item = (int)atomicAdd(&d_work, 1u);
            item = __shfl_sync(FULL, item, 0);
            bool pass = false;
            if (item < NITEMS && lane < GG) {
                int pi = item / 3;
                int b  = pi >> 6;
                int p  = pi & 63;
                const float* pb2 = pr + (size_t)(b*PP + p)*4;
                float px_ = pb2[0], py_ = pb2[1], pw_ = pb2[2], ph_ = pb2[3];
                const float* gb = gt + (size_t)(b*GG + lane)*4;
                float gx = gb[0], gy = gb[1], gw_ = gb[2], gh_ = gb[3];
                float tlx = fmaxf(gx - gw_*0.5f, px_ - pw_*0.5f);
                float tly = fmaxf(gy - gh_*0.5f, py_ - ph_*0.5f);
                float brx = fminf(gx + gw_*0.5f, px_ + pw_*0.5f);
                float bry = fminf(gy + gh_*0.5f, py_ + ph_*0.5f);
                float en  = ((tlx < brx) && (tly < bry)) ? 1.0f : 0.0f;
                float ai  = (brx - tlx) * (bry - tly) * en;
                float iou = ai / (gw_*gh_ + pw_*ph_ - ai + 1e-16f);
                pass = (iou > 0.3f) && (pw_ > 2.0f) && (ph_ > 2.0f);
            }
            unsigned msk = __ballot_sync(FULL, pass);
            if (lane == 0) { s_item[it & 1] = item; s_mask[it & 1] = msk; }
        }
        __syncthreads();                  // pop + mask visible to all
        int      item = s_item[it & 1];
        unsigned mask = s_mask[it & 1];
        it++;
        if (item >= NITEMS) break;

        int nm = __popc((int)mask);
        if (nm == 0) continue;            // next write goes to the other slot

        int c  = item % 3;
        int pi = item / 3;
        int b  = pi >> 6;
        int p  = pi & 63;
        if (t == 0 && c == 0) cntloc += nm;

        const float* imc = imgs + ((size_t)b * 3 + c) * IMH * IMW;
        const float* pb  = pr + (size_t)(b*PP + p)*4;
        const float* gtb = gt + (size_t)(b*GG)*4;

        // pred crop: channel fixed per item -> hoist out of gt loop
        float pxA, pxB;
        crop_pair(imc, pb, hrow, c0, pxA, pxB);

        for (int m = 0; m < nm; m++) {
            int buf = m & 1;
            int g = __ffs((int)mask) - 1;
            mask &= mask - 1u;
            float gyA, gyB;
            crop_pair(imc, gtb + (size_t)g*4, hrow, c0, gyA, gyB);

            // sum/difference basis: s=x+y, e=x-y. Fields {s, e, s^2, e^2}.
            float sA = pxA + gyA, eA = pxA - gyA;
            float sB = pxB + gyB, eB = pxB - gyB;

            // L1 term: |x-y|/255
            accf = fmaf(fabsf(eA), 1.0f/255.0f, accf);
            accf = fmaf(fabsf(eB), 1.0f/255.0f, accf);

            // H-pass: each remote neighbor value fetched once (2 shuffles: s,e)
            // and applied to both owned pixels. Half-warp boundary == patch
            // boundary, so the lane guards double as zero-pad guards.
            float h0a, h1a, h2a, h3a, h0b, h1b, h2b, h3b;
            {   // local taps
                float sA2 = sA*sA, eA2 = eA*eA, sB2 = sB*sB, eB2 = eB*eB;
                h0a = fmaf(GW[1], sB,  GW[0]*sA);
                h1a = fmaf(GW[1], eB,  GW[0]*eA);
                h2a = fmaf(GW[1], sB2, GW[0]*sA2);
                h3a = fmaf(GW[1], eB2, GW[0]*eA2);
                h0b = fmaf(GW[1], sA,  GW[0]*sB);
                h1b = fmaf(GW[1], eA,  GW[0]*eB);
                h2b = fmaf(GW[1], sA2, GW[0]*sB2);
                h3b = fmaf(GW[1], eA2, GW[0]*eB2);
            }
            #define HAPPLY2(vs, ve, ok, WA, WB)                                  \
                do { if (ok) { float _s2 = (vs)*(vs), _e2 = (ve)*(ve);           \
                    h0a = fmaf(WA, (vs), h0a); h1a = fmaf(WA, (ve), h1a);        \
                    h2a = fmaf(WA, _s2,  h2a); h3a = fmaf(WA, _e2,  h3a);        \
                    h0b = fmaf(WB, (vs), h0b); h1b = fmaf(WB, (ve), h1b);        \
                    h2b = fmaf(WB, _s2,  h2b); h3b = fmaf(WB, _e2,  h3b); } } while(0)
            #define HAPPLYA(vs, ve, ok, WA)                                      \
                do { if (ok) { float _s2 = (vs)*(vs), _e2 = (ve)*(ve);           \
                    h0a = fmaf(WA, (vs), h0a); h1a = fmaf(WA, (ve), h1a);        \
                    h2a = fmaf(WA, _s2,  h2a); h3a = fmaf(WA, _e2,  h3a); } } while(0)
            #define HAPPLYB(vs, ve, ok, WB)                                      \
                do { if (ok) { float _s2 = (vs)*(vs), _e2 = (ve)*(ve);           \
                    h0b = fmaf(WB, (vs), h0b); h1b = fmaf(WB, (ve), h1b);        \
                    h2b = fmaf(WB, _s2,  h2b); h3b = fmaf(WB, _e2,  h3b); } } while(0)
            {   // col 2cp+2 (a:+2, b:+1)
                float vs = __shfl_down_sync(FULL, sA, 1);
                float ve = __shfl_down_sync(FULL, eA, 1);
                HAPPLY2(vs, ve, cp <= 14, GW[2], GW[1]);
            }
            {   // col 2cp+3 (a:+3, b:+2)
                float vs = __shfl_down_sync(FULL, sB, 1);
                float ve = __shfl_down_sync(FULL, eB, 1);
                HAPPLY2(vs, ve, cp <= 14, GW[3], GW[2]);
            }
            {   // col 2cp+4 (a:+4, b:+3)
                float vs = __shfl_down_sync(FULL, sA, 2);
                float ve = __shfl_down_sync(FULL, eA, 2);
                HAPPLY2(vs, ve, cp <= 13, GW[4], GW[3]);
            }
            {   // col 2cp+5 (a:+5, b:+4)
                float vs = __shfl_down_sync(FULL, sB, 2);
                float ve = __shfl_down_sync(FULL, eB, 2);
                HAPPLY2(vs, ve, cp <= 13, GW[5], GW[4]);
            }
            {   // col 2cp+6 (b:+5 only)
                float vs = __shfl_down_sync(FULL, sA, 3);
                float ve = __shfl_down_sync(FULL, eA, 3);
                HAPPLYB(vs, ve, cp <= 12, GW[5]);
            }
            {   // col 2cp-1 (a:-1, b:-2)
                float vs = __shfl_up_sync(FULL, sB, 1);
                float ve = __shfl_up_sync(FULL, eB, 1);
                HAPPLY2(vs, ve, cp >= 1, GW[1], GW[2]);
            }
            {   // col 2cp-2 (a:-2, b:-3)
                float vs = __shfl_up_sync(FULL, sA, 1);
                float ve = __shfl_up_sync(FULL, eA, 1);
                HAPPLY2(vs, ve, cp >= 1, GW[2], GW[3]);
            }
            {   // col 2cp-3 (a:-3, b:-4)
                float vs = __shfl_up_sync(FULL, sB, 2);
                float ve = __shfl_up_sync(FULL, eB, 2);
                HAPPLY2(vs, ve, cp >= 2, GW[3], GW[4]);
            }
            {   // col 2cp-4 (a:-4, b:-5)
                float vs = __shfl_up_sync(FULL, sA, 2);
                float ve = __shfl_up_sync(FULL, eA, 2);
                HAPPLY2(vs, ve, cp >= 2, GW[4], GW[5]);
            }
            {   // col 2cp-5 (a:-5 only)
                float vs = __shfl_up_sync(FULL, sB, 3);
                float ve = __shfl_up_sync(FULL, eB, 3);
                HAPPLYA(vs, ve, cp >= 3, GW[5]);
            }
            #undef HAPPLY2
            #undef HAPPLYA
            #undef HAPPLYB

            int kst = (hrow + 5) * SZ + c0;   // padded row index
            Hb[buf][kst]     = make_float4(h0a, h1a, h2a, h3a);
            Hb[buf][kst + 1] = make_float4(h0b, h1b, h2b, h3b);
            __syncthreads();   // single barrier per gt (double buffer)

            // V-pass mapping: col = lane, rows r0 and r0+1 share tap loads.
            float v00=0.f,v01=0.f,v02=0.f,v03=0.f;
            float v10=0.f,v11=0.f,v12=0.f,v13=0.f;
            #pragma unroll
            for (int dd = 0; dd <= 11; dd++) {
                int k = (r0 + dd) * SZ + lane;
                float4 f = Hb[buf][k];
                if (dd <= 10) {                    // tap for output row r0
                    const float wv = GW[dd < 5 ? 5 - dd : dd - 5];
                    v00 = fmaf(wv, f.x, v00);
                    v01 = fmaf(wv, f.y, v01);
                    v02 = fmaf(wv, f.z, v02);
                    v03 = fmaf(wv, f.w, v03);
                }
                if (dd >= 1) {                     // tap for output row r0+1
                    const float wv = GW[dd < 6 ? 6 - dd : dd - 6];
                    v10 = fmaf(wv, f.x, v10);
                    v11 = fmaf(wv, f.y, v11);
                    v12 = fmaf(wv, f.z, v12);
                    v13 = fmaf(wv, f.w, v13);
                }
            }

            // SSIM in s/d basis, constants folded. A=S^2+D^2, B=S^2-D^2:
            //   ssim = ((B/2+C1)(U-V-B+2C2)) / ((A/2+C1)(U+V-A+2C2))
            float ssimA, ssimB;
            {
                float S2 = v00*v00, D2 = v01*v01;
                float A = S2 + D2, B = S2 - D2;
                ssimA = __fdividef((fmaf(0.5f, B, C1)) * (v02 - v03 - B + C2x2),
                                   (fmaf(0.5f, A, C1)) * (v02 + v03 - A + C2x2));
            }
            {
                float S2 = v10*v10, D2 = v11*v11;
                float A = S2 + D2, B = S2 - D2;
                ssimB = __fdividef((fmaf(0.5f, B, C1)) * (v12 - v13 - B + C2x2),
                                   (fmaf(0.5f, A, C1)) * (v12 + v13 - A + C2x2));
            }
            accf += 2.0f - ssimA - ssimB;
            // no trailing barrier: next gt writes the other buffer
        }
    }

    // ---- one block reduction at the end (16 warps) ----
    #pragma unroll
    for (int o = 16; o > 0; o >>= 1) accf += __shfl_down_sync(FULL, accf, o);
    if (lane == 0) sred[warp] = accf;
    __syncthreads();
    if (t < 16) {
        float v = sred[t];
        #pragma unroll
        for (int o = 8; o > 0; o >>= 1) v += __shfl_down_sync(0xffffu, v, o);
        if (t == 0) {
            if (v != 0.0f)  atomicAdd(&d_total, (double)v);
            if (cntloc > 0) atomicAdd(&d_cnt, (double)cntloc);
        }
    }

    // completion counter: last block finalizes and resets all globals
    __threadfence();
    if (t == 0) {
        unsigned prev = atomicAdd(&d_done, 1u);
        s_last = (prev == (unsigned)(NPBLOCKS - 1));
    }
    __syncthreads();
    if (s_last && t == 0) {
        double cnt = d_cnt * (double)(3*SZ*SZ);
        out[0] = (cnt > 0.0) ? (float)(d_total / fmax(cnt, 1.0)) : 0.0f;
        d_total = 0.0;
        d_cnt   = 0.0;
        d_done  = 0u;
        d_work  = 0u;
    }
}

extern "C" void kernel_launch(void* const* d_in, const int* in_sizes, int n_in,
                              void* d_out, int out_size) {
    const float* gt   = (const float*)d_in[0];
    const float* pr   = (const float*)d_in[1];
    const float* imgs = (const float*)d_in[2];
    float* out = (float*)d_out;

    fused_kernel<<<NPBLOCKS, 512>>>(gt, pr, imgs, out);
}